// round 4
// baseline (speedup 1.0000x reference)
#include <cuda_runtime.h>
#include <math.h>

// Problem constants
#define Bq   8
#define Cc   64
#define Hh   256
#define Ww   256
#define HWs  65536        // H*W
#define CHW  4194304      // C*H*W
#define CTAS_PER_BATCH 16
#define COUT_PER_CTA   4  // 64 / 16
#define THREADS 256
#define ROWSTRIDE 264     // floats per channel row in smem (4 pad front, data [4..259], sentinels at 3 and 260)
#define ROW_SMEM_FLOATS (Cc * ROWSTRIDE)               // 16896
#define W_SMEM_FLOATS   (Cc * COUT_PER_CTA * 4)        // 1024 (float4 per (cin,cout))
#define SMEM_BYTES ((ROW_SMEM_FLOATS + W_SMEM_FLOATS) * 4)

// Per-batch software barrier state. Zero-initialized at module load.
// g_cnt returns to 0 at the end of every barrier round (last arriver resets),
// g_gen is monotonic across launches; each launch reads its base at start.
__device__ unsigned int g_cnt[Bq];
__device__ unsigned int g_gen[Bq];

__device__ __forceinline__ float tanh_fast(float x) {
    // accurate to ~1e-6 rel, no NaN for large |x| (expf(inf) -> 2/inf = 0)
    float ax = fabsf(x);
    float e  = __expf(2.0f * ax);
    float t  = 1.0f - 2.0f / (e + 1.0f);
    return copysignf(t, x);
}

// Load one full row (64 channels x 256 w) from global (channel stride HWs floats)
// into smem row buffer. src points at (c=0, h, w=0).
__device__ __forceinline__ void load_row(float* __restrict__ sX,
                                         const float* __restrict__ src, int tid) {
#pragma unroll
    for (int i = 0; i < 16; i++) {
        int idx = i * THREADS + tid;   // 0..4095 float4 slots
        int cin = idx >> 6;            // 64 float4 per channel
        int wq  = idx & 63;
        float4 v = *reinterpret_cast<const float4*>(src + cin * HWs + (wq << 2));
        *reinterpret_cast<float4*>(sX + cin * ROWSTRIDE + 4 + (wq << 2)) = v;
    }
}

__global__ void __launch_bounds__(THREADS, 1)
spatial_conv_kernel(const float* __restrict__ X,
                    const float* __restrict__ Wc,   // [64][64][3]
                    const float* __restrict__ bc,   // [64]
                    float* __restrict__ Y)
{
    extern __shared__ float smem[];
    float*  sX  = smem;                        // row buffer
    float4* wS4 = reinterpret_cast<float4*>(smem + ROW_SMEM_FLOATS); // [cin][cout] -> (k0,k1,k2,0)

    const int tid = threadIdx.x;
    const int b   = blockIdx.x >> 4;           // batch
    const int r   = blockIdx.x & 15;           // cta rank within batch
    const int c0  = r * COUT_PER_CTA;          // first output channel
    const int w   = tid;                       // each thread owns one w

    // --- one-time setup ---------------------------------------------------
    // halo sentinels (w = -1 and w = 256 read as zero)
    if (tid < Cc) {
        sX[tid * ROWSTRIDE + 3]   = 0.0f;
        sX[tid * ROWSTRIDE + 260] = 0.0f;
    }
    // stage this CTA's weights into smem as float4 (k0,k1,k2,0)
    {
        int cin = tid >> 2;          // 0..63
        int co  = tid & 3;           // 0..3
        const float* wp = Wc + ((c0 + co) * Cc + cin) * 3;
        wS4[cin * COUT_PER_CTA + co] = make_float4(wp[0], wp[1], wp[2], 0.0f);
    }

    const float bz0 = bc[c0 + 0];
    const float bz1 = bc[c0 + 1];
    const float bz2 = bc[c0 + 2];
    const float bz3 = bc[c0 + 3];

    unsigned int genbase = 0;
    if (tid == 0) genbase = *((volatile unsigned int*)&g_gen[b]);

    const float* Xb = X + b * CHW;
    float*       Yb = Y + b * CHW;

    // row 0: Y[0] = X[0] (this CTA's channel slice), and stage full row 0 in smem
    load_row(sX, Xb /* h = 0 */, tid);
#pragma unroll
    for (int j = 0; j < COUT_PER_CTA; j++) {
        Yb[(c0 + j) * HWs + w] = Xb[(c0 + j) * HWs + w];
    }
    __syncthreads();

    // --- recurrence over rows --------------------------------------------
    for (int h = 1; h < Hh; h++) {
        // prefetch X for this row's outputs (hidden under the conv)
        const float* xrow = Xb + h * Ww;
        float xi0 = xrow[(c0 + 0) * HWs + w];
        float xi1 = xrow[(c0 + 1) * HWs + w];
        float xi2 = xrow[(c0 + 2) * HWs + w];
        float xi3 = xrow[(c0 + 3) * HWs + w];

        float a0 = bz0, a1 = bz1, a2 = bz2, a3 = bz3;

#pragma unroll 8
        for (int cin = 0; cin < Cc; cin++) {
            const float* xs = sX + cin * ROWSTRIDE + 3 + w;  // [w-1, w, w+1]
            float xl = xs[0];
            float xc = xs[1];
            float xr = xs[2];
            float4 w0 = wS4[cin * COUT_PER_CTA + 0];
            float4 w1 = wS4[cin * COUT_PER_CTA + 1];
            float4 w2 = wS4[cin * COUT_PER_CTA + 2];
            float4 w3 = wS4[cin * COUT_PER_CTA + 3];
            a0 += w0.x * xl; a0 += w0.y * xc; a0 += w0.z * xr;
            a1 += w1.x * xl; a1 += w1.y * xc; a1 += w1.z * xr;
            a2 += w2.x * xl; a2 += w2.y * xc; a2 += w2.z * xr;
            a3 += w3.x * xl; a3 += w3.y * xc; a3 += w3.z * xr;
        }

        float* yrow = Yb + h * Ww;
        yrow[(c0 + 0) * HWs + w] = xi0 + tanh_fast(a0);
        yrow[(c0 + 1) * HWs + w] = xi1 + tanh_fast(a1);
        yrow[(c0 + 2) * HWs + w] = xi2 + tanh_fast(a2);
        yrow[(c0 + 3) * HWs + w] = xi3 + tanh_fast(a3);

        if (h == Hh - 1) break;  // last row: no one consumes it inside the kernel

        // all threads of this CTA done writing + done reading smem row
        __syncthreads();

        // per-batch barrier across the 16 CTAs (sense via monotonic generation)
        if (tid == 0) {
            __threadfence();  // make this CTA's row writes visible gpu-wide
            unsigned int old = atomicAdd(&g_cnt[b], 1u);
            if (old == CTAS_PER_BATCH - 1u) {
                atomicExch(&g_cnt[b], 0u);   // reset for next round
                __threadfence();
                atomicAdd(&g_gen[b], 1u);    // release the round
            } else {
                unsigned int target = genbase + (unsigned int)h;
                while (*((volatile unsigned int*)&g_gen[b]) < target) { }
            }
            __threadfence();  // order subsequent row loads after the release
        }
        __syncthreads();

        // pull the freshly completed row h (all 64 channels) into smem
        load_row(sX, Yb + h * Ww, tid);
        __syncthreads();
    }
}

extern "C" void kernel_launch(void* const* d_in, const int* in_sizes, int n_in,
                              void* d_out, int out_size)
{
    const float* X  = (const float*)d_in[0];
    const float* Wc = (const float*)d_in[1];
    const float* bc = (const float*)d_in[2];
    float*       Y  = (float*)d_out;
    (void)in_sizes; (void)n_in; (void)out_size;

    cudaFuncSetAttribute(spatial_conv_kernel,
                         cudaFuncAttributeMaxDynamicSharedMemorySize, SMEM_BYTES);

    spatial_conv_kernel<<<Bq * CTAS_PER_BATCH, THREADS, SMEM_BYTES>>>(X, Wc, bc, Y);
}

// round 5
// speedup vs baseline: 1.1703x; 1.1703x over previous
#include <cuda_runtime.h>
#include <math.h>

// Problem constants
#define Bq   8
#define Cc   64
#define Hh   256
#define Ww   256
#define HWs  65536        // H*W
#define CHW  4194304      // C*H*W
#define CTAS_PER_BATCH 16
#define T_W  16           // w columns per CTA
#define GROUPS 16         // cout groups (4 couts each)
#define THREADS 256
#define RSTR 20           // smem row stride per channel: [0]=left halo, [1..16]=data, [17]=right halo
#define ROW_SMEM_FLOATS (Cc * RSTR)                     // 1280
#define W_SMEM_F4       (GROUPS * Cc * 3)               // 3072 float4 = 48 KB
#define SMEM_BYTES ((ROW_SMEM_FLOATS * 4) + (W_SMEM_F4 * 16))

// halo[b][r][side][parity][ch] : side 0 = CTA r's leftmost column (for neighbor r-1),
//                               side 1 = CTA r's rightmost column (for neighbor r+1)
__device__ float        g_halo[Bq][CTAS_PER_BATCH][2][2][Cc];
// monotonic "rows completed" counter per CTA; +256 per launch, uniform across CTAs
__device__ unsigned int g_flag[Bq][CTAS_PER_BATCH];

__device__ __forceinline__ float tanh_fast(float x) {
    float ax = fabsf(x);
    float e  = __expf(2.0f * ax);
    float t  = 1.0f - 2.0f / (e + 1.0f);
    return copysignf(t, x);
}

__device__ __forceinline__ float vload_f(const float* p) {
    return *((volatile const float*)p);   // bypass L1 (parity slots recur)
}
__device__ __forceinline__ unsigned int vload_u(const unsigned int* p) {
    return *((volatile const unsigned int*)p);
}

__global__ void __launch_bounds__(THREADS, 1)
spatial_conv_kernel(const float* __restrict__ X,
                    const float* __restrict__ Wc,   // [64][64][3]
                    const float* __restrict__ bc,   // [64]
                    float* __restrict__ Y)
{
    extern __shared__ float smem[];
    float*  sRow = smem;                                         // [64][RSTR]
    float4* wS4  = reinterpret_cast<float4*>(smem + ROW_SMEM_FLOATS); // [g][cin][3] float4 (4 couts per tap)

    const int tid = threadIdx.x;
    const int b   = blockIdx.x >> 4;
    const int r   = blockIdx.x & 15;
    const int w   = tid & 15;          // local column 0..15
    const int g   = tid >> 4;          // cout group 0..15
    const int c0  = g * 4;             // first of 4 couts
    const int wg  = r * T_W + w;       // global column

    // ---- stage weights: wS4[(g*64+cin)*3 + tap] = (k_tap for couts 4g..4g+3) ----
    for (int idx = tid; idx < W_SMEM_F4; idx += THREADS) {
        int gg  = idx / (Cc * 3);
        int rem = idx - gg * (Cc * 3);
        int cin = rem / 3;
        int tap = rem - cin * 3;
        float4 v;
        v.x = Wc[((4 * gg + 0) * Cc + cin) * 3 + tap];
        v.y = Wc[((4 * gg + 1) * Cc + cin) * 3 + tap];
        v.z = Wc[((4 * gg + 2) * Cc + cin) * 3 + tap];
        v.w = Wc[((4 * gg + 3) * Cc + cin) * 3 + tap];
        wS4[idx] = v;
    }

    const float bz0 = bc[c0 + 0];
    const float bz1 = bc[c0 + 1];
    const float bz2 = bc[c0 + 2];
    const float bz3 = bc[c0 + 3];

    unsigned int base = 0;
    if (tid < 2) base = vload_u(&g_flag[b][r]);   // own flag == all CTAs' start value

    const float* Xb = X + b * CHW;
    float*       Yb = Y + b * CHW;

    // ---- row 0: Y[0] = X[0] ----
    {
        float y0 = Xb[(c0 + 0) * HWs + wg];
        float y1 = Xb[(c0 + 1) * HWs + wg];
        float y2 = Xb[(c0 + 2) * HWs + wg];
        float y3 = Xb[(c0 + 3) * HWs + wg];
        Yb[(c0 + 0) * HWs + wg] = y0;
        Yb[(c0 + 1) * HWs + wg] = y1;
        Yb[(c0 + 2) * HWs + wg] = y2;
        Yb[(c0 + 3) * HWs + wg] = y3;
        sRow[(c0 + 0) * RSTR + 1 + w] = y0;
        sRow[(c0 + 1) * RSTR + 1 + w] = y1;
        sRow[(c0 + 2) * RSTR + 1 + w] = y2;
        sRow[(c0 + 3) * RSTR + 1 + w] = y3;
        if (w == 0) {
            float* hp = &g_halo[b][r][0][0][c0];
            hp[0] = y0; hp[1] = y1; hp[2] = y2; hp[3] = y3;
            __threadfence();
        }
        if (w == 15) {
            float* hp = &g_halo[b][r][1][0][c0];
            hp[0] = y0; hp[1] = y1; hp[2] = y2; hp[3] = y3;
            __threadfence();
        }
    }
    __syncthreads();
    // publish row 0 + wait for neighbors' row 0
    if (tid == 0) {
        atomicExch(&g_flag[b][r], base + 1u);
        if (r > 0) { unsigned int tgt = base + 1u;
            while ((int)(vload_u(&g_flag[b][r - 1]) - tgt) < 0) { } }
    } else if (tid == 1) {
        if (r < 15) { unsigned int tgt = base + 1u;
            while ((int)(vload_u(&g_flag[b][r + 1]) - tgt) < 0) { } }
    }
    __syncthreads();
    // pull row-0 halos
    if (tid < Cc) {
        float v = 0.0f;
        if (r > 0) v = vload_f(&g_halo[b][r - 1][1][0][tid]);
        sRow[tid * RSTR + 0] = v;
    } else if (tid < 2 * Cc) {
        int ch = tid - Cc;
        float v = 0.0f;
        if (r < 15) v = vload_f(&g_halo[b][r + 1][0][0][ch]);
        sRow[ch * RSTR + 17] = v;
    }
    __syncthreads();

    // ---- recurrence ----
    for (int h = 1; h < Hh; h++) {
        // prefetch X for this row's outputs
        const float* xrow = Xb + h * Ww + wg;
        float xi0 = xrow[(c0 + 0) * HWs];
        float xi1 = xrow[(c0 + 1) * HWs];
        float xi2 = xrow[(c0 + 2) * HWs];
        float xi3 = xrow[(c0 + 3) * HWs];

        float a0 = bz0, a1 = bz1, a2 = bz2, a3 = bz3;

        const float*  xp = sRow + w;         // [w]=xl, [w+1]=xc, [w+2]=xr
        const float4* wp = wS4 + g * (Cc * 3);
#pragma unroll 8
        for (int cin = 0; cin < Cc; cin++) {
            float xl = xp[0];
            float xc = xp[1];
            float xr = xp[2];
            float4 K0 = wp[0];
            float4 K1 = wp[1];
            float4 K2 = wp[2];
            a0 = fmaf(K0.x, xl, a0); a0 = fmaf(K1.x, xc, a0); a0 = fmaf(K2.x, xr, a0);
            a1 = fmaf(K0.y, xl, a1); a1 = fmaf(K1.y, xc, a1); a1 = fmaf(K2.y, xr, a1);
            a2 = fmaf(K0.z, xl, a2); a2 = fmaf(K1.z, xc, a2); a2 = fmaf(K2.z, xr, a2);
            a3 = fmaf(K0.w, xl, a3); a3 = fmaf(K1.w, xc, a3); a3 = fmaf(K2.w, xr, a3);
            xp += RSTR;
            wp += 3;
        }

        float y0 = xi0 + tanh_fast(a0);
        float y1 = xi1 + tanh_fast(a1);
        float y2 = xi2 + tanh_fast(a2);
        float y3 = xi3 + tanh_fast(a3);

        float* yrow = Yb + h * Ww + wg;
        yrow[(c0 + 0) * HWs] = y0;
        yrow[(c0 + 1) * HWs] = y1;
        yrow[(c0 + 2) * HWs] = y2;
        yrow[(c0 + 3) * HWs] = y3;

        if (h == Hh - 1) {
            // maintain flag invariant (+256 per launch), nothing left to exchange
            if (tid == 0) atomicExch(&g_flag[b][r], base + 256u);
            break;
        }

        __syncthreads();   // everyone done reading sRow (row h-1)

        // write row h into smem + publish edge columns
        sRow[(c0 + 0) * RSTR + 1 + w] = y0;
        sRow[(c0 + 1) * RSTR + 1 + w] = y1;
        sRow[(c0 + 2) * RSTR + 1 + w] = y2;
        sRow[(c0 + 3) * RSTR + 1 + w] = y3;
        const int par = h & 1;
        if (w == 0) {
            float* hp = &g_halo[b][r][0][par][c0];
            hp[0] = y0; hp[1] = y1; hp[2] = y2; hp[3] = y3;
            __threadfence();
        }
        if (w == 15) {
            float* hp = &g_halo[b][r][1][par][c0];
            hp[0] = y0; hp[1] = y1; hp[2] = y2; hp[3] = y3;
            __threadfence();
        }
        __syncthreads();

        // flag + neighbor spin (two threads spin in parallel)
        if (tid == 0) {
            atomicExch(&g_flag[b][r], base + (unsigned int)h + 1u);
            if (r > 0) { unsigned int tgt = base + (unsigned int)h + 1u;
                while ((int)(vload_u(&g_flag[b][r - 1]) - tgt) < 0) { } }
        } else if (tid == 1) {
            if (r < 15) { unsigned int tgt = base + (unsigned int)h + 1u;
                while ((int)(vload_u(&g_flag[b][r + 1]) - tgt) < 0) { } }
        }
        __syncthreads();

        // pull neighbor halos for row h (volatile: parity slots recur in L1)
        if (tid < Cc) {
            float v = 0.0f;
            if (r > 0) v = vload_f(&g_halo[b][r - 1][1][par][tid]);
            sRow[tid * RSTR + 0] = v;
        } else if (tid < 2 * Cc) {
            int ch = tid - Cc;
            float v = 0.0f;
            if (r < 15) v = vload_f(&g_halo[b][r + 1][0][par][ch]);
            sRow[ch * RSTR + 17] = v;
        }
        __syncthreads();
    }
}

extern "C" void kernel_launch(void* const* d_in, const int* in_sizes, int n_in,
                              void* d_out, int out_size)
{
    const float* X  = (const float*)d_in[0];
    const float* Wc = (const float*)d_in[1];
    const float* bc = (const float*)d_in[2];
    float*       Y  = (float*)d_out;
    (void)in_sizes; (void)n_in; (void)out_size;

    cudaFuncSetAttribute(spatial_conv_kernel,
                         cudaFuncAttributeMaxDynamicSharedMemorySize, SMEM_BYTES);

    spatial_conv_kernel<<<Bq * CTAS_PER_BATCH, THREADS, SMEM_BYTES>>>(X, Wc, bc, Y);
}